// round 8
// baseline (speedup 1.0000x reference)
#include <cuda_runtime.h>
#include <cstdint>

#define B_BATCH 2
#define SEQ 2048
#define EMBED 1024
#define HEADS 16
#define HDIM 64
#define MROWS (B_BATCH * SEQ)   // 4096

// ---------------- scratch (device globals: allocation-free) ----------------
__device__ float g_Qr[(size_t)MROWS * EMBED];                  // tf32-rounded query
__device__ float g_Q[(size_t)MROWS * EMBED];
__device__ float g_K[(size_t)MROWS * EMBED];
__device__ float g_V[(size_t)MROWS * EMBED];
__device__ float g_O[(size_t)MROWS * EMBED];
__device__ float g_Wt[(size_t)4 * EMBED * EMBED];              // transposed weights (tf32)
__device__ float g_Vt[(size_t)B_BATCH * HEADS * HDIM * SEQ];   // V transposed per head (tf32)
__device__ float g_qsq[(size_t)B_BATCH * HEADS * SEQ];
__device__ float g_ksq[(size_t)B_BATCH * HEADS * SEQ];

// ======================= helpers =======================
__device__ __forceinline__ uint32_t smem_u32(const void* p) {
    uint32_t a;
    asm("{ .reg .u64 t; cvta.to.shared.u64 t, %1; cvt.u32.u64 %0, t; }" : "=r"(a) : "l"(p));
    return a;
}
__device__ __forceinline__ float to_tf32(float x) {
    float r; asm("cvt.rna.tf32.f32 %0, %1;" : "=f"(r) : "f"(x)); return r;
}
__device__ __forceinline__ void cp_async16(uint32_t dst, const void* src) {
    asm volatile("cp.async.cg.shared.global [%0], [%1], 16;" :: "r"(dst), "l"(src));
}
#define CP_COMMIT() asm volatile("cp.async.commit_group;" ::: "memory")
#define CP_WAIT0()  asm volatile("cp.async.wait_group 0;" ::: "memory")

// mma.sync m16n8k8 tf32: D += A*B  (A row-major m16k8, B col-major k8n8)
__device__ __forceinline__ void mma_tf32(float* d, const uint32_t* a, const uint32_t* b) {
    asm volatile(
        "mma.sync.aligned.m16n8k8.row.col.f32.tf32.tf32.f32 "
        "{%0,%1,%2,%3}, {%4,%5,%6,%7}, {%8,%9}, {%0,%1,%2,%3};"
        : "+f"(d[0]), "+f"(d[1]), "+f"(d[2]), "+f"(d[3])
        : "r"(a[0]), "r"(a[1]), "r"(a[2]), "r"(a[3]), "r"(b[0]), "r"(b[1]));
}
__device__ __forceinline__ uint32_t ldsf(const float* p) { return __float_as_uint(*p); }

// ======================= round query to tf32 =======================
__global__ __launch_bounds__(256) void round_query_kernel(const float* __restrict__ in)
{
    size_t i = ((size_t)blockIdx.x * 256 + threadIdx.x) * 4;
    float4 v = *(const float4*)&in[i];
    v.x = to_tf32(v.x); v.y = to_tf32(v.y); v.z = to_tf32(v.z); v.w = to_tf32(v.w);
    *(float4*)&g_Qr[i] = v;
}

// ======================= transpose weights (+tf32 round) =======================
__global__ __launch_bounds__(256) void transpose_w_kernel(
    const float* __restrict__ wq, const float* __restrict__ wk,
    const float* __restrict__ wv, const float* __restrict__ wo)
{
    __shared__ float t[32][33];
    const int z = blockIdx.z;
    const float* W = (z == 0) ? wq : (z == 1) ? wk : (z == 2) ? wv : wo;
    float* Out = g_Wt + (size_t)z * EMBED * EMBED;
    const int k0 = blockIdx.x * 32, n0 = blockIdx.y * 32;
    const int tx = threadIdx.x & 31, ty = threadIdx.x >> 5;
#pragma unroll
    for (int i = 0; i < 4; i++)
        t[ty + i * 8][tx] = W[(size_t)(k0 + ty + i * 8) * EMBED + n0 + tx];
    __syncthreads();
#pragma unroll
    for (int i = 0; i < 4; i++)
        Out[(size_t)(n0 + ty + i * 8) * EMBED + k0 + tx] = to_tf32(t[tx][ty + i * 8]);
}

// ======================= transpose V per head (+tf32 round) =======================
__global__ __launch_bounds__(256) void transpose_v_kernel()
{
    __shared__ float t[32][33];
    const int b = blockIdx.z;
    const int e0 = blockIdx.x * 32, s0 = blockIdx.y * 32;
    const int tx = threadIdx.x & 31, ty = threadIdx.x >> 5;
#pragma unroll
    for (int i = 0; i < 4; i++)
        t[ty + i * 8][tx] = g_V[(size_t)(b * SEQ + s0 + ty + i * 8) * EMBED + e0 + tx];
    __syncthreads();
#pragma unroll
    for (int i = 0; i < 4; i++) {
        int e = e0 + ty + i * 8;
        int s = s0 + tx;
        g_Vt[(size_t)(b * HEADS + (e >> 6)) * HDIM * SEQ + (size_t)(e & 63) * SEQ + s] =
            to_tf32(t[tx][ty + i * 8]);
    }
}

// ======================= per-row squared norms =======================
__global__ __launch_bounds__(256) void norms_kernel()
{
    int gw = (blockIdx.x * 256 + threadIdx.x) >> 5;
    int lane = threadIdx.x & 31;
    int z = gw / SEQ, s = gw % SEQ;
    int b = z / HEADS, h = z % HEADS;
    size_t off = (size_t)(b * SEQ + s) * EMBED + h * HDIM + lane * 2;
    float2 q = *(const float2*)&g_Q[off];
    float2 k = *(const float2*)&g_K[off];
    float qs = q.x * q.x + q.y * q.y;
    float ks = k.x * k.x + k.y * k.y;
#pragma unroll
    for (int o = 16; o > 0; o >>= 1) {
        qs += __shfl_xor_sync(0xffffffffu, qs, o);
        ks += __shfl_xor_sync(0xffffffffu, ks, o);
    }
    if (lane == 0) { g_qsq[gw] = qs; g_ksq[gw] = ks; }
}

// ======================= tf32 mma.sync projection GEMM (64x128 tile) =======================
// Block tile 64x128, BK=32, 256 threads, 8 warps (32x32 each), 2-stage cp.async.
// Smem per stage: As[64][36] + Bs[128][36] floats = 27648 B; total 55296 B.
#define PROJ_SMEM 55296

__global__ __launch_bounds__(256, 3) void proj64_kernel(
    const float* __restrict__ A,
    const float* __restrict__ B0, const float* __restrict__ B1, const float* __restrict__ B2,
    const float* __restrict__ bias0, const float* __restrict__ bias1, const float* __restrict__ bias2,
    float* __restrict__ C0, float* __restrict__ C1, float* __restrict__ C2,
    int roundMask)
{
    extern __shared__ __align__(16) float smf[];
    const int z = blockIdx.z;
    const float* Bt = (z == 0) ? B0 : (z == 1) ? B1 : B2;
    const float* bias = (z == 0) ? bias0 : (z == 1) ? bias1 : bias2;
    float* C = (z == 0) ? C0 : (z == 1) ? C1 : C2;
    const bool doRound = (roundMask >> z) & 1;

    float* Abuf[2] = { smf,          smf + 6912 };   // 6912 floats per stage
    float* Bbuf[2] = { smf + 2304,   smf + 6912 + 2304 };
    const uint32_t sAu[2] = { smem_u32(Abuf[0]), smem_u32(Abuf[1]) };
    const uint32_t sBu[2] = { smem_u32(Bbuf[0]), smem_u32(Bbuf[1]) };

    const int tid = threadIdx.x, lane = tid & 31, warp = tid >> 5;
    const int g = lane >> 2, tg = lane & 3;
    const int m0 = blockIdx.y * 64, n0 = blockIdx.x * 128;
    const int mw = (warp >> 2) * 32, nw = (warp & 3) * 32;

    float acc[2][4][4];
#pragma unroll
    for (int mi = 0; mi < 2; mi++)
#pragma unroll
        for (int ni = 0; ni < 4; ni++)
#pragma unroll
            for (int c = 0; c < 4; c++) acc[mi][ni][c] = 0.f;

    auto issue = [&](int kc) {
        const int buf = kc & 1;
        const int k0 = kc * 32;
#pragma unroll
        for (int it = 0; it < 2; it++) {
            int idx = tid + it * 256;
            int r = idx >> 3, c = idx & 7;
            cp_async16(sAu[buf] + r * 144 + c * 16, &A[(size_t)(m0 + r) * EMBED + k0 + c * 4]);
        }
#pragma unroll
        for (int it = 0; it < 4; it++) {
            int idx = tid + it * 256;
            int r = idx >> 3, c = idx & 7;
            cp_async16(sBu[buf] + r * 144 + c * 16, &Bt[(size_t)(n0 + r) * EMBED + k0 + c * 4]);
        }
        CP_COMMIT();
    };

    issue(0);
    for (int kc = 0; kc < 32; kc++) {
        CP_WAIT0();
        __syncthreads();
        if (kc + 1 < 32) issue(kc + 1);
        const float* As = Abuf[kc & 1];
        const float* Bs = Bbuf[kc & 1];
#pragma unroll
        for (int ks = 0; ks < 4; ks++) {
            const int k = ks * 8;
            uint32_t af[2][4], bf[4][2];
#pragma unroll
            for (int mi = 0; mi < 2; mi++) {
                const float* ap = &As[(mw + mi * 16 + g) * 36 + k + tg];
                af[mi][0] = ldsf(ap);
                af[mi][1] = ldsf(ap + 8 * 36);
                af[mi][2] = ldsf(ap + 4);
                af[mi][3] = ldsf(ap + 8 * 36 + 4);
            }
#pragma unroll
            for (int ni = 0; ni < 4; ni++) {
                const float* bp = &Bs[(nw + ni * 8 + g) * 36 + k + tg];
                bf[ni][0] = ldsf(bp);
                bf[ni][1] = ldsf(bp + 4);
            }
#pragma unroll
            for (int mi = 0; mi < 2; mi++)
#pragma unroll
                for (int ni = 0; ni < 4; ni++)
                    mma_tf32(acc[mi][ni], af[mi], bf[ni]);
        }
    }

#pragma unroll
    for (int mi = 0; mi < 2; mi++)
#pragma unroll
        for (int ni = 0; ni < 4; ni++) {
            int row = m0 + mw + mi * 16 + g;
            int col = n0 + nw + ni * 8 + tg * 2;
            float b0 = bias[col], b1 = bias[col + 1];
            float2 v0, v1;
            v0.x = acc[mi][ni][0] + b0; v0.y = acc[mi][ni][1] + b1;
            v1.x = acc[mi][ni][2] + b0; v1.y = acc[mi][ni][3] + b1;
            if (doRound) {
                v0.x = to_tf32(v0.x); v0.y = to_tf32(v0.y);
                v1.x = to_tf32(v1.x); v1.y = to_tf32(v1.y);
            }
            *(float2*)&C[(size_t)row * EMBED + col] = v0;
            *(float2*)&C[(size_t)(row + 8) * EMBED + col] = v1;
        }
}

// ======================= fused attention v2 (512 threads, double-buffered) =======================
// One (b,h), one 128-row q-tile per block; 32 k-tiles of 64 k-positions.
// Smem (bytes): Qs[128][68] @0 | Ks[2][64][68] @34816 | Vts[2][64][68] @69632 |
//               Ps[128][68] @104448 | ksq[2][64] @139264 | lsum[128][4] @139776
#define AT_Q    0
#define AT_K    34816
#define AT_V    69632
#define AT_P    104448
#define AT_KSQ  139264
#define AT_LSUM 139776
#define AT_BYTES 141824

__global__ __launch_bounds__(512, 1) void attention_kernel(const float* __restrict__ tempPtr)
{
    extern __shared__ __align__(16) char smc[];
    float* Qs   = (float*)(smc + AT_Q);
    float* Ps   = (float*)(smc + AT_P);
    float* ksqs = (float*)(smc + AT_KSQ);
    float* lsum = (float*)(smc + AT_LSUM);
    const uint32_t sQ = smem_u32(smc + AT_Q);
    const uint32_t sK = smem_u32(smc + AT_K);
    const uint32_t sV = smem_u32(smc + AT_V);

    const int tid = threadIdx.x, lane = tid & 31, warp = tid >> 5;
    const int g = lane >> 2, tg = lane & 3;
    // S-phase mapping: 4x4 warp grid over S[128][64]
    const int smw = (warp >> 2) * 32;
    const int snw = (warp & 3) * 16;
    // O-phase mapping: split-k (kh) x 4x2 warp grid over O[128][64]
    const int kh  = warp >> 3;
    const int w8  = warp & 7;
    const int omw = (w8 >> 1) * 32;
    const int onw = (w8 & 1) * 32;

    const int z = blockIdx.y;
    const int b = z / HEADS, h = z % HEADS;
    const int q0 = blockIdx.x * 128;
    const float invT = 1.0f / (*tempPtr);
    const size_t vtoff = (size_t)z * HDIM * SEQ;

    // ---- prologue: Q tile (group), tile 0 K/V (group) ----
#pragma unroll
    for (int it = 0; it < 4; it++) {
        int idx = tid + it * 512;
        int r = idx >> 4, c = idx & 15;
        cp_async16(sQ + r * 272 + c * 16,
                   &g_Q[(size_t)(b * SEQ + q0 + r) * EMBED + h * HDIM + c * 4]);
    }
    CP_COMMIT();
    {
#pragma unroll
        for (int it = 0; it < 2; it++) {
            int idx = tid + it * 512;
            int r = idx >> 4, c = idx & 15;
            cp_async16(sK + r * 272 + c * 16,
                       &g_K[(size_t)(b * SEQ + r) * EMBED + h * HDIM + c * 4]);
            cp_async16(sV + r * 272 + c * 16,
                       &g_Vt[vtoff + (size_t)r * SEQ + c * 4]);
        }
        CP_COMMIT();
    }

    float qqv[4];
#pragma unroll
    for (int mi = 0; mi < 2; mi++) {
        qqv[mi * 2 + 0] = g_qsq[(size_t)z * SEQ + q0 + smw + mi * 16 + g];
        qqv[mi * 2 + 1] = g_qsq[(size_t)z * SEQ + q0 + smw + mi * 16 + g + 8];
    }

    float oacc[2][4][4];
#pragma unroll
    for (int mi = 0; mi < 2; mi++)
#pragma unroll
        for (int ni = 0; ni < 4; ni++)
#pragma unroll
            for (int c = 0; c < 4; c++) oacc[mi][ni][c] = 0.f;
    float rsum[4] = {0.f, 0.f, 0.f, 0.f};

    for (int kt = 0; kt < 32; kt++) {
        const int buf = kt & 1;
        const int kk0 = kt * 64;
        // ksq for this tile (double-buffered; write BEFORE barrier)
        if (tid < 16) {
            float4 v = *(const float4*)&g_ksq[(size_t)z * SEQ + kk0 + tid * 4];
            *(float4*)&ksqs[buf * 64 + tid * 4] = v;
        }
        CP_WAIT0();
        __syncthreads();
        // prefetch next tile
        if (kt + 1 < 32) {
            const int nbuf = (kt + 1) & 1;
            const int nk0 = (kt + 1) * 64;
#pragma unroll
            for (int it = 0; it < 2; it++) {
                int idx = tid + it * 512;
                int r = idx >> 4, c = idx & 15;
                cp_async16(sK + nbuf * 17408 + r * 272 + c * 16,
                           &g_K[(size_t)(b * SEQ + nk0 + r) * EMBED + h * HDIM + c * 4]);
                cp_async16(sV + nbuf * 17408 + r * 272 + c * 16,
                           &g_Vt[vtoff + (size_t)r * SEQ + nk0 + c * 4]);
            }
            CP_COMMIT();
        }

        const float* Ks  = (const float*)(smc + AT_K + buf * 17408);
        const float* Vts = (const float*)(smc + AT_V + buf * 17408);
        const float* ksq = &ksqs[buf * 64];

        // ---- S = Q @ K^T (warp: 32x16 of S[128][64]) ----
        float sacc[2][2][4];
#pragma unroll
        for (int mi = 0; mi < 2; mi++)
#pragma unroll
            for (int nj = 0; nj < 2; nj++)
#pragma unroll
                for (int c = 0; c < 4; c++) sacc[mi][nj][c] = 0.f;
#pragma unroll
        for (int ks = 0; ks < 8; ks++) {
            const int k = ks * 8;
            uint32_t af[2][4], bf[2][2];
#pragma unroll
            for (int mi = 0; mi < 2; mi++) {
                const float* ap = &Qs[(smw + mi * 16 + g) * 68 + k + tg];
                af[mi][0] = ldsf(ap);
                af[mi][1] = ldsf(ap + 8 * 68);
                af[mi][2] = ldsf(ap + 4);
                af[mi][3] = ldsf(ap + 8 * 68 + 4);
            }
#pragma unroll
            for (int nj = 0; nj < 2; nj++) {
                const float* bp = &Ks[(snw + nj * 8 + g) * 68 + k + tg];
                bf[nj][0] = ldsf(bp);
                bf[nj][1] = ldsf(bp + 4);
            }
#pragma unroll
            for (int mi = 0; mi < 2; mi++)
#pragma unroll
                for (int nj = 0; nj < 2; nj++)
                    mma_tf32(sacc[mi][nj], af[mi], bf[nj]);
        }

        // ---- epilogue: p = exp(-max(qq+kk-2s,0)/T) -> Ps ----
#pragma unroll
        for (int mi = 0; mi < 2; mi++) {
            const int rlo = smw + mi * 16 + g, rhi = rlo + 8;
            const float qlo = qqv[mi * 2], qhi = qqv[mi * 2 + 1];
#pragma unroll
            for (int nj = 0; nj < 2; nj++) {
                const int col = snw + nj * 8 + tg * 2;
                const float kc0 = ksq[col], kc1 = ksq[col + 1];
                float p00 = __expf(-fmaxf(qlo + kc0 - 2.f * sacc[mi][nj][0], 0.f) * invT);
                float p01 = __expf(-fmaxf(qlo + kc1 - 2.f * sacc[mi][nj][1], 0.f) * invT);
                float p10 = __expf(-fmaxf(qhi + kc0 - 2.f * sacc[mi][nj][2], 0.f) * invT);
                float p11 = __expf(-fmaxf(qhi + kc1 - 2.f * sacc[mi][nj][3], 0.f) * invT);
                rsum[mi * 2 + 0] += p00 + p01;
                rsum[mi * 2 + 1] += p10 + p11;
                float2 w0 = { to_tf32(p00), to_tf32(p01) };
                float2 w1 = { to_tf32(p10), to_tf32(p11) };
                *(float2*)&Ps[rlo * 68 + col] = w0;
                *(float2*)&Ps[rhi * 68 + col] = w1;
            }
        }
        __syncthreads();

        // ---- O += P @ V (warp: 32x32 of O[128][64], split-k over 64) ----
#pragma unroll
        for (int ks = 0; ks < 4; ks++) {
            const int k = kh * 32 + ks * 8;
            uint32_t paf[2][4], vbf[4][2];
#pragma unroll
            for (int mi = 0; mi < 2; mi++) {
                const float* ap = &Ps[(omw + mi * 16 + g) * 68 + k + tg];
                paf[mi][0] = ldsf(ap);
                paf[mi][1] = ldsf(ap + 8 * 68);
                paf[mi][2] = ldsf(ap + 4);
                paf[mi][3] = ldsf(ap + 8 * 68 + 4);
            }
#pragma unroll
            for (int ni = 0; ni < 4; ni++) {
                const float* bp = &Vts[(onw + ni * 8 + g) * 68 + k + tg];
                vbf[ni][0] = ldsf(bp);
                vbf[ni][1] = ldsf(bp + 4);
            }
#pragma unroll
            for (int mi = 0; mi < 2; mi++)
#pragma unroll
                for (int ni = 0; ni < 4; ni++)
                    mma_tf32(oacc[mi][ni], paf[mi], vbf[ni]);
        }
    }

    __syncthreads();   // all PV reads of Ps done

    // ---- row-sum reduce: shfl over tg, then across 4 n-quarters via lsum ----
#pragma unroll
    for (int i = 0; i < 4; i++) {
        rsum[i] += __shfl_xor_sync(0xffffffffu, rsum[i], 1);
        rsum[i] += __shfl_xor_sync(0xffffffffu, rsum[i], 2);
    }
    if (tg == 0) {
#pragma unroll
        for (int mi = 0; mi < 2; mi++) {
            lsum[(smw + mi * 16 + g) * 4 + (warp & 3)]     = rsum[mi * 2 + 0];
            lsum[(smw + mi * 16 + g + 8) * 4 + (warp & 3)] = rsum[mi * 2 + 1];
        }
    }
    __syncthreads();

    float linv[4];
#pragma unroll
    for (int mi = 0; mi < 2; mi++) {
        int rlo = omw + mi * 16 + g, rhi = rlo + 8;
        linv[mi * 2 + 0] = 1.f / (lsum[rlo * 4] + lsum[rlo * 4 + 1] + lsum[rlo * 4 + 2] + lsum[rlo * 4 + 3]);
        linv[mi * 2 + 1] = 1.f / (lsum[rhi * 4] + lsum[rhi * 4 + 1] + lsum[rhi * 4 + 2] + lsum[rhi * 4 + 3]);
    }

    // ---- split-k reduce via Ps, then scale + round + store ----
    if (kh == 1) {
#pragma unroll
        for (int mi = 0; mi < 2; mi++)
#pragma unroll
            for (int ni = 0; ni < 4; ni++) {
                int rlo = omw + mi * 16 + g, rhi = rlo + 8;
                int col = onw + ni * 8 + tg * 2;
                float2 w0 = { oacc[mi][ni][0], oacc[mi][ni][1] };
                float2 w1 = { oacc[mi][ni][2], oacc[mi][ni][3] };
                *(float2*)&Ps[rlo * 68 + col] = w0;
                *(float2*)&Ps[rhi * 68 + col] = w1;
            }
    }
    __syncthreads();
    if (kh == 0) {
#pragma unroll
        for (int mi = 0; mi < 2; mi++)
#pragma unroll
            for (int ni = 0; ni < 4; ni++) {
                int rlo = omw + mi * 16 + g, rhi = rlo + 8;
                int col = onw + ni * 8 + tg * 2;
                float2 p0 = *(float2*)&Ps[rlo * 68 + col];
                float2 p1 = *(float2*)&Ps[rhi * 68 + col];
                float2 w0, w1;
                w0.x = to_tf32((oacc[mi][ni][0] + p0.x) * linv[mi * 2]);
                w0.y = to_tf32((oacc[mi][ni][1] + p0.y) * linv[mi * 2]);
                w1.x = to_tf32((oacc[mi][ni][2] + p1.x) * linv[mi * 2 + 1]);
                w1.y = to_tf32((oacc[mi][ni][3] + p1.y) * linv[mi * 2 + 1]);
                *(float2*)&g_O[(size_t)(b * SEQ + q0 + rlo) * EMBED + h * HDIM + col] = w0;
                *(float2*)&g_O[(size_t)(b * SEQ + q0 + rhi) * EMBED + h * HDIM + col] = w1;
            }
    }
}

// ======================= launcher =======================
extern "C" void kernel_launch(void* const* d_in, const int* in_sizes, int n_in,
                              void* d_out, int out_size)
{
    const float* query = (const float*)d_in[0];
    const float* wq = (const float*)d_in[1];
    const float* bq = (const float*)d_in[2];
    const float* wk = (const float*)d_in[3];
    const float* bk = (const float*)d_in[4];
    const float* wv = (const float*)d_in[5];
    const float* bv = (const float*)d_in[6];
    const float* wo = (const float*)d_in[7];
    const float* bo = (const float*)d_in[8];
    const float* temperature = (const float*)d_in[9];
    float* out = (float*)d_out;

    cudaFuncSetAttribute(attention_kernel,
                         cudaFuncAttributeMaxDynamicSharedMemorySize, AT_BYTES);
    cudaFuncSetAttribute(proj64_kernel,
                         cudaFuncAttributeMaxDynamicSharedMemorySize, PROJ_SMEM);

    float *Qrp, *Qp, *Kp, *Vp, *Op, *Wtp;
    cudaGetSymbolAddress((void**)&Qrp, g_Qr);
    cudaGetSymbolAddress((void**)&Qp, g_Q);
    cudaGetSymbolAddress((void**)&Kp, g_K);
    cudaGetSymbolAddress((void**)&Vp, g_V);
    cudaGetSymbolAddress((void**)&Op, g_O);
    cudaGetSymbolAddress((void**)&Wtp, g_Wt);
    const float *W0 = Wtp, *W1 = Wtp + (size_t)EMBED * EMBED,
                *W2 = Wtp + 2 * (size_t)EMBED * EMBED, *W3 = Wtp + 3 * (size_t)EMBED * EMBED;

    round_query_kernel<<<(MROWS * EMBED) / (256 * 4), 256>>>(query);

    dim3 gTW(EMBED / 32, EMBED / 32, 4);
    transpose_w_kernel<<<gTW, 256>>>(wq, wk, wv, wo);

    // fused QKV projection: grid (8 n, 64 m, 3 z); round all three outputs
    dim3 gQKV(EMBED / 128, MROWS / 64, 3);
    proj64_kernel<<<gQKV, 256, PROJ_SMEM>>>(Qrp, W0, W1, W2, bq, bk, bv, Qp, Kp, Vp, 0x7);

    norms_kernel<<<(B_BATCH * HEADS * SEQ) / 8, 256>>>();

    dim3 gTV(EMBED / 32, SEQ / 32, B_BATCH);
    transpose_v_kernel<<<gTV, 256>>>();

    dim3 gAtt(SEQ / 128, B_BATCH * HEADS);    // (16, 32)
    attention_kernel<<<gAtt, 512, AT_BYTES>>>(temperature);

    // output projection: no rounding
    dim3 gOut(EMBED / 128, MROWS / 64, 1);
    proj64_kernel<<<gOut, 256, PROJ_SMEM>>>(Op, W3, W3, W3, bo, bo, bo, out, out, out, 0x0);
}

// round 10
// speedup vs baseline: 1.2571x; 1.2571x over previous
#include <cuda_runtime.h>
#include <cstdint>

#define B_BATCH 2
#define SEQ 2048
#define EMBED 1024
#define HEADS 16
#define HDIM 64
#define MROWS (B_BATCH * SEQ)   // 4096

// ---------------- scratch (device globals: allocation-free) ----------------
__device__ float g_Qr[(size_t)MROWS * EMBED];                  // tf32-rounded query
__device__ float g_Q[(size_t)MROWS * EMBED];
__device__ float g_K[(size_t)MROWS * EMBED];
__device__ float g_V[(size_t)MROWS * EMBED];
__device__ float g_O[(size_t)MROWS * EMBED];
__device__ float g_Wt[(size_t)4 * EMBED * EMBED];              // transposed weights (tf32)
__device__ float g_Vt[(size_t)B_BATCH * HEADS * HDIM * SEQ];   // V transposed per head (tf32)
__device__ float g_qsq[(size_t)B_BATCH * HEADS * SEQ];
__device__ float g_ksq[(size_t)B_BATCH * HEADS * SEQ];

// ======================= helpers =======================
__device__ __forceinline__ uint32_t smem_u32(const void* p) {
    uint32_t a;
    asm("{ .reg .u64 t; cvta.to.shared.u64 t, %1; cvt.u32.u64 %0, t; }" : "=r"(a) : "l"(p));
    return a;
}
__device__ __forceinline__ float to_tf32(float x) {
    float r; asm("cvt.rna.tf32.f32 %0, %1;" : "=f"(r) : "f"(x)); return r;
}
__device__ __forceinline__ void cp_async16(uint32_t dst, const void* src) {
    asm volatile("cp.async.cg.shared.global [%0], [%1], 16;" :: "r"(dst), "l"(src));
}
#define CP_COMMIT() asm volatile("cp.async.commit_group;" ::: "memory")
#define CP_WAIT0()  asm volatile("cp.async.wait_group 0;" ::: "memory")
#define CP_WAIT1()  asm volatile("cp.async.wait_group 1;" ::: "memory")

// mma.sync m16n8k8 tf32: D += A*B  (A row-major m16k8, B col-major k8n8)
__device__ __forceinline__ void mma_tf32(float* d, const uint32_t* a, const uint32_t* b) {
    asm volatile(
        "mma.sync.aligned.m16n8k8.row.col.f32.tf32.tf32.f32 "
        "{%0,%1,%2,%3}, {%4,%5,%6,%7}, {%8,%9}, {%0,%1,%2,%3};"
        : "+f"(d[0]), "+f"(d[1]), "+f"(d[2]), "+f"(d[3])
        : "r"(a[0]), "r"(a[1]), "r"(a[2]), "r"(a[3]), "r"(b[0]), "r"(b[1]));
}
__device__ __forceinline__ uint32_t ldsf(const float* p) { return __float_as_uint(*p); }

__device__ __forceinline__ void ldmx4(uint32_t* r, uint32_t addr) {
    asm volatile("ldmatrix.sync.aligned.m8n8.x4.shared.b16 {%0,%1,%2,%3}, [%4];"
        : "=r"(r[0]), "=r"(r[1]), "=r"(r[2]), "=r"(r[3]) : "r"(addr));
}

// ======================= round query to tf32 =======================
__global__ __launch_bounds__(256) void round_query_kernel(const float* __restrict__ in)
{
    size_t i = ((size_t)blockIdx.x * 256 + threadIdx.x) * 4;
    float4 v = *(const float4*)&in[i];
    v.x = to_tf32(v.x); v.y = to_tf32(v.y); v.z = to_tf32(v.z); v.w = to_tf32(v.w);
    *(float4*)&g_Qr[i] = v;
}

// ======================= transpose weights (+tf32 round) =======================
__global__ __launch_bounds__(256) void transpose_w_kernel(
    const float* __restrict__ wq, const float* __restrict__ wk,
    const float* __restrict__ wv, const float* __restrict__ wo)
{
    __shared__ float t[32][33];
    const int z = blockIdx.z;
    const float* W = (z == 0) ? wq : (z == 1) ? wk : (z == 2) ? wv : wo;
    float* Out = g_Wt + (size_t)z * EMBED * EMBED;
    const int k0 = blockIdx.x * 32, n0 = blockIdx.y * 32;
    const int tx = threadIdx.x & 31, ty = threadIdx.x >> 5;
#pragma unroll
    for (int i = 0; i < 4; i++)
        t[ty + i * 8][tx] = W[(size_t)(k0 + ty + i * 8) * EMBED + n0 + tx];
    __syncthreads();
#pragma unroll
    for (int i = 0; i < 4; i++)
        Out[(size_t)(n0 + ty + i * 8) * EMBED + k0 + tx] = to_tf32(t[tx][ty + i * 8]);
}

// ======================= transpose V per head (+tf32 round) =======================
__global__ __launch_bounds__(256) void transpose_v_kernel()
{
    __shared__ float t[32][33];
    const int b = blockIdx.z;
    const int e0 = blockIdx.x * 32, s0 = blockIdx.y * 32;
    const int tx = threadIdx.x & 31, ty = threadIdx.x >> 5;
#pragma unroll
    for (int i = 0; i < 4; i++)
        t[ty + i * 8][tx] = g_V[(size_t)(b * SEQ + s0 + ty + i * 8) * EMBED + e0 + tx];
    __syncthreads();
#pragma unroll
    for (int i = 0; i < 4; i++) {
        int e = e0 + ty + i * 8;
        int s = s0 + tx;
        g_Vt[(size_t)(b * HEADS + (e >> 6)) * HDIM * SEQ + (size_t)(e & 63) * SEQ + s] =
            to_tf32(t[tx][ty + i * 8]);
    }
}

// ======================= per-row squared norms =======================
__global__ __launch_bounds__(256) void norms_kernel()
{
    int gw = (blockIdx.x * 256 + threadIdx.x) >> 5;
    int lane = threadIdx.x & 31;
    int z = gw / SEQ, s = gw % SEQ;
    int b = z / HEADS, h = z % HEADS;
    size_t off = (size_t)(b * SEQ + s) * EMBED + h * HDIM + lane * 2;
    float2 q = *(const float2*)&g_Q[off];
    float2 k = *(const float2*)&g_K[off];
    float qs = q.x * q.x + q.y * q.y;
    float ks = k.x * k.x + k.y * k.y;
#pragma unroll
    for (int o = 16; o > 0; o >>= 1) {
        qs += __shfl_xor_sync(0xffffffffu, qs, o);
        ks += __shfl_xor_sync(0xffffffffu, ks, o);
    }
    if (lane == 0) { g_qsq[gw] = qs; g_ksq[gw] = ks; }
}

// ======================= tf32 mma.sync projection GEMM (128x128, ldmatrix, 3-stage) ======
// Block 128x128, BK=32, 256 threads, 8 warps (64x32 each), 3-stage cp.async.
// Smem: 3 stages x (A 128x36 + B 128x36) floats = 110592 B.
#define PROJ_STAGE_F (128 * 36 * 2)           // floats per stage (A then B)
#define PROJ_SMEM    (3 * PROJ_STAGE_F * 4)   // 110592 bytes

__global__ __launch_bounds__(256, 2) void proj_ldm_kernel(
    const float* __restrict__ A,
    const float* __restrict__ B0, const float* __restrict__ B1, const float* __restrict__ B2,
    const float* __restrict__ bias0, const float* __restrict__ bias1, const float* __restrict__ bias2,
    float* __restrict__ C0, float* __restrict__ C1, float* __restrict__ C2,
    int roundMask)
{
    extern __shared__ __align__(16) float smf[];
    const int z = blockIdx.z;
    const float* Bt = (z == 0) ? B0 : (z == 1) ? B1 : B2;
    const float* bias = (z == 0) ? bias0 : (z == 1) ? bias1 : bias2;
    float* C = (z == 0) ? C0 : (z == 1) ? C1 : C2;
    const bool doRound = (roundMask >> z) & 1;

    const uint32_t sBase = smem_u32(smf);
    const int tid = threadIdx.x, lane = tid & 31, warp = tid >> 5;
    const int g = lane >> 2, tg = lane & 3;
    const int m0 = blockIdx.y * 128, n0 = blockIdx.x * 128;
    const int mw = (warp >> 2) * 64, nw = (warp & 3) * 32;

    // ldmatrix lane offsets (bytes) within a stage
    const uint32_t aOff = ((mw + (lane & 15)) * 36 + ((lane >> 4) << 2)) * 4;
    const uint32_t bOff = 18432 +
        ((nw + (lane & 7) + ((lane >> 4) << 3)) * 36 + (((lane >> 3) & 1) << 2)) * 4;

    float acc[4][4][4];
#pragma unroll
    for (int mi = 0; mi < 4; mi++)
#pragma unroll
        for (int ni = 0; ni < 4; ni++)
#pragma unroll
            for (int c = 0; c < 4; c++) acc[mi][ni][c] = 0.f;

    auto issue = [&](int kc) {
        const uint32_t sb = sBase + (kc % 3) * (PROJ_STAGE_F * 4);
        const int k0 = kc * 32;
#pragma unroll
        for (int it = 0; it < 4; it++) {
            int idx = tid + it * 256;
            int r = idx >> 3, c = idx & 7;
            cp_async16(sb + r * 144 + c * 16, &A[(size_t)(m0 + r) * EMBED + k0 + c * 4]);
            cp_async16(sb + 18432 + r * 144 + c * 16, &Bt[(size_t)(n0 + r) * EMBED + k0 + c * 4]);
        }
        CP_COMMIT();
    };

    issue(0); issue(1);
    for (int kc = 0; kc < 32; kc++) {
        if (kc == 31) { CP_WAIT0(); } else { CP_WAIT1(); }
        __syncthreads();
        if (kc + 2 < 32) issue(kc + 2);
        const uint32_t sb = sBase + (kc % 3) * (PROJ_STAGE_F * 4);
#pragma unroll
        for (int ks = 0; ks < 4; ks++) {
            const uint32_t kb = ks * 32;     // 8 floats
            uint32_t af[4][4], bf[4][2];
#pragma unroll
            for (int mi = 0; mi < 4; mi++)
                ldmx4(af[mi], sb + aOff + mi * 2304 + kb);   // 16 rows * 144 B = 2304 B
            {
                uint32_t t0[4], t1[4];
                ldmx4(t0, sb + bOff + kb);
                ldmx4(t1, sb + bOff + 2304 + kb);
                bf[0][0] = t0[0]; bf[0][1] = t0[1]; bf[1][0] = t0[2]; bf[1][1] = t0[3];
                bf[2][0] = t1[0]; bf[2][1] = t1[1]; bf[3][0] = t1[2]; bf[3][1] = t1[3];
            }
#pragma unroll
            for (int mi = 0; mi < 4; mi++)
#pragma unroll
                for (int ni = 0; ni < 4; ni++)
                    mma_tf32(acc[mi][ni], af[mi], bf[ni]);
        }
        __syncthreads();
    }

#pragma unroll
    for (int mi = 0; mi < 4; mi++)
#pragma unroll
        for (int ni = 0; ni < 4; ni++) {
            int row = m0 + mw + mi * 16 + g;
            int col = n0 + nw + ni * 8 + tg * 2;
            float b0 = bias[col], b1 = bias[col + 1];
            float2 v0, v1;
            v0.x = acc[mi][ni][0] + b0; v0.y = acc[mi][ni][1] + b1;
            v1.x = acc[mi][ni][2] + b0; v1.y = acc[mi][ni][3] + b1;
            if (doRound) {
                v0.x = to_tf32(v0.x); v0.y = to_tf32(v0.y);
                v1.x = to_tf32(v1.x); v1.y = to_tf32(v1.y);
            }
            *(float2*)&C[(size_t)row * EMBED + col] = v0;
            *(float2*)&C[(size_t)(row + 8) * EMBED + col] = v1;
        }
}

// ======================= fused attention (tf32 mma.sync) — R6 structure =======================
// Per block: one (b,h), one 128-row q-tile; 16 k-tiles of 128.
// Smem (floats): Qs[128][68] | Ks[128][68] | Vts[64][132] | Ps[128][132] | ksq[128] | lsum[128][2]
#define SM_Q    0
#define SM_K    34816
#define SM_VT   69632
#define SM_P    103424
#define SM_KSQ  171008
#define SM_LSUM 171520
#define SM_ATT_BYTES 172544

__global__ __launch_bounds__(256, 1) void attention_kernel(const float* __restrict__ tempPtr)
{
    extern __shared__ __align__(16) char smc[];
    float* Qs  = (float*)(smc + SM_Q);
    float* Ks  = (float*)(smc + SM_K);
    float* Vts = (float*)(smc + SM_VT);
    float* Ps  = (float*)(smc + SM_P);
    float* ksq = (float*)(smc + SM_KSQ);
    float* lsum = (float*)(smc + SM_LSUM);
    const uint32_t sQ = smem_u32(Qs), sK = smem_u32(Ks), sVT = smem_u32(Vts);

    const int tid = threadIdx.x, lane = tid & 31, warp = tid >> 5;
    const int g = lane >> 2, tg = lane & 3;
    const int mw = (warp >> 1) * 32;
    const int nhalf = warp & 1;
    const int nw = nhalf * 64;
    const int nwo = nhalf * 32;

    const int z = blockIdx.y;
    const int b = z / HEADS, h = z % HEADS;
    const int q0 = blockIdx.x * 128;
    const float invT = 1.0f / (*tempPtr);

#pragma unroll
    for (int it = 0; it < 8; it++) {
        int idx = tid + it * 256;
        int r = idx >> 4, c = idx & 15;
        cp_async16(sQ + r * 272 + c * 16,
                   &g_Q[(size_t)(b * SEQ + q0 + r) * EMBED + h * HDIM + c * 4]);
    }
    CP_COMMIT();

    float qqv[4];
#pragma unroll
    for (int mi = 0; mi < 2; mi++) {
        qqv[mi * 2 + 0] = g_qsq[(size_t)z * SEQ + q0 + mw + mi * 16 + g];
        qqv[mi * 2 + 1] = g_qsq[(size_t)z * SEQ + q0 + mw + mi * 16 + g + 8];
    }

    float oacc[2][4][4];
#pragma unroll
    for (int mi = 0; mi < 2; mi++)
#pragma unroll
        for (int ni = 0; ni < 4; ni++)
#pragma unroll
            for (int c = 0; c < 4; c++) oacc[mi][ni][c] = 0.f;
    float rsum[4] = {0.f, 0.f, 0.f, 0.f};

    for (int kt = 0; kt < 16; kt++) {
        const int kk0 = kt * 128;
        __syncthreads();
#pragma unroll
        for (int it = 0; it < 8; it++) {
            int idx = tid + it * 256;
            {
                int r = idx >> 4, c = idx & 15;
                cp_async16(sK + r * 272 + c * 16,
                           &g_K[(size_t)(b * SEQ + kk0 + r) * EMBED + h * HDIM + c * 4]);
            }
            {
                int r = idx >> 5, c = idx & 31;
                cp_async16(sVT + r * 528 + c * 16,
                           &g_Vt[(size_t)z * HDIM * SEQ + (size_t)r * SEQ + kk0 + c * 4]);
            }
        }
        CP_COMMIT();
        if (tid < 32) {
            float4 v = ((const float4*)&g_ksq[(size_t)z * SEQ + kk0])[tid];
            ((float4*)ksq)[tid] = v;
        }
        CP_WAIT0();
        __syncthreads();

        // ---- S = Q @ K^T (warp: 32x64) ----
        float sacc[2][8][4];
#pragma unroll
        for (int mi = 0; mi < 2; mi++)
#pragma unroll
            for (int nj = 0; nj < 8; nj++)
#pragma unroll
                for (int c = 0; c < 4; c++) sacc[mi][nj][c] = 0.f;
#pragma unroll
        for (int ks = 0; ks < 8; ks++) {
            const int k = ks * 8;
            uint32_t af[2][4], bf[8][2];
#pragma unroll
            for (int mi = 0; mi < 2; mi++) {
                const float* ap = &Qs[(mw + mi * 16 + g) * 68 + k + tg];
                af[mi][0] = ldsf(ap);
                af[mi][1] = ldsf(ap + 8 * 68);
                af[mi][2] = ldsf(ap + 4);
                af[mi][3] = ldsf(ap + 8 * 68 + 4);
            }
#pragma unroll
            for (int nj = 0; nj < 8; nj++) {
                const float* bp = &Ks[(nw + nj * 8 + g) * 68 + k + tg];
                bf[nj][0] = ldsf(bp);
                bf[nj][1] = ldsf(bp + 4);
            }
#pragma unroll
            for (int mi = 0; mi < 2; mi++)
#pragma unroll
                for (int nj = 0; nj < 8; nj++)
                    mma_tf32(sacc[mi][nj], af[mi], bf[nj]);
        }

        // ---- epilogue: p = exp(-max(qq+kk-2s,0)/T), write P ----
#pragma unroll
        for (int mi = 0; mi < 2; mi++) {
            const int rlo = mw + mi * 16 + g, rhi = rlo + 8;
            const float qlo = qqv[mi * 2], qhi = qqv[mi * 2 + 1];
#pragma unroll
            for (int nj = 0; nj < 8; nj++) {
                const int col = nw + nj * 8 + tg * 2;
                const float kc0 = ksq[col], kc1 = ksq[col + 1];
                float p00 = __expf(-fmaxf(qlo + kc0 - 2.f * sacc[mi][nj][0], 0.f) * invT);
                float p01 = __expf(-fmaxf(qlo + kc1 - 2.f * sacc[mi][nj][1], 0.f) * invT);
                float p10 = __expf(-fmaxf(qhi + kc0 - 2.f * sacc[mi][nj][2], 0.f) * invT);
                float p11 = __expf(-fmaxf(qhi + kc1 - 2.f * sacc[mi][nj][3], 0.f) * invT);
                rsum[mi * 2 + 0] += p00 + p01;
                rsum[mi * 2 + 1] += p10 + p11;
                float2 w0 = { to_tf32(p00), to_tf32(p01) };
                float2 w1 = { to_tf32(p10), to_tf32(p11) };
                *(float2*)&Ps[rlo * 132 + col] = w0;
                *(float2*)&Ps[rhi * 132 + col] = w1;
            }
        }
        __syncthreads();

        // ---- O += P @ V (warp: 32x32, k=128) ----
#pragma unroll
        for (int ks = 0; ks < 16; ks++) {
            const int k = ks * 8;
            uint32_t paf[2][4], vbf[4][2];
#pragma unroll
            for (int mi = 0; mi < 2; mi++) {
                const float* ap = &Ps[(mw + mi * 16 + g) * 132 + k + tg];
                paf[mi][0] = ldsf(ap);
                paf[mi][1] = ldsf(ap + 8 * 132);
                paf[mi][2] = ldsf(ap + 4);
                paf[mi][3] = ldsf(ap + 8 * 132 + 4);
            }
#pragma unroll
            for (int ni = 0; ni < 4; ni++) {
                const float* bp = &Vts[(nwo + ni * 8 + g) * 132 + k + tg];
                vbf[ni][0] = ldsf(bp);
                vbf[ni][1] = ldsf(bp + 4);
            }
#pragma unroll
            for (int mi = 0; mi < 2; mi++)
#pragma unroll
                for (int ni = 0; ni < 4; ni++)
                    mma_tf32(oacc[mi][ni], paf[mi], vbf[ni]);
        }
    }

#pragma unroll
    for (int i = 0; i < 4; i++) {
        rsum[i] += __shfl_xor_sync(0xffffffffu, rsum[i], 1);
        rsum[i] += __shfl_xor_sync(0xffffffffu, rsum[i], 2);
    }
    __syncthreads();
    if (tg == 0) {
#pragma unroll
        for (int mi = 0; mi < 2; mi++) {
            lsum[(mw + mi * 16 + g) * 2 + nhalf]     = rsum[mi * 2 + 0];
            lsum[(mw + mi * 16 + g + 8) * 2 + nhalf] = rsum[mi * 2 + 1];
        }
    }
    __syncthreads();

    float linv[4];
#pragma unroll
    for (int mi = 0; mi < 2; mi++) {
        int rlo = mw + mi * 16 + g, rhi = rlo + 8;
        linv[mi * 2 + 0] = 1.f / (lsum[rlo * 2] + lsum[rlo * 2 + 1]);
        linv[mi * 2 + 1] = 1.f / (lsum[rhi * 2] + lsum[rhi * 2 + 1]);
    }

#pragma unroll
    for (int mi = 0; mi < 2; mi++)
#pragma unroll
        for (int ni = 0; ni < 4; ni++) {
            int rlo = mw + mi * 16 + g, rhi = rlo + 8;
            int col = nwo + ni * 8 + tg * 2;
            float2 w0, w1;
            w0.x = to_tf32(oacc[mi][ni][0] * linv[mi * 2]);
            w0.y = to_tf32(oacc[mi][ni][1] * linv[mi * 2]);
            w1.x = to_tf32(oacc[mi][ni][2] * linv[mi * 2 + 1]);
            w1.y = to_tf32(oacc[mi][ni][3] * linv[mi * 2 + 1]);
            *(float2*)&g_O[(size_t)(b * SEQ + q0 + rlo) * EMBED + h * HDIM + col] = w0;
            *(float2*)&g_O[(size_t)(b * SEQ + q0 + rhi) * EMBED + h * HDIM + col] = w1;
        }
}

// ======================= launcher =======================
extern "C" void kernel_launch(void* const* d_in, const int* in_sizes, int n_in,
                              void* d_out, int out_size)
{
    const float* query = (const float*)d_in[0];
    const float* wq = (const float*)d_in[1];
    const float* bq = (const float*)d_in[2];
    const float* wk = (const float*)d_in[3];
    const float* bk = (const float*)d_in[4];
    const float* wv = (const float*)d_in[5];
    const float* bv = (const float*)d_in[6];
    const float* wo = (const float*)d_in[7];
    const float* bo = (const float*)d_in[8];
    const float* temperature = (const float*)d_in[9];
    float* out = (float*)d_out;

    cudaFuncSetAttribute(attention_kernel,
                         cudaFuncAttributeMaxDynamicSharedMemorySize, SM_ATT_BYTES);
    cudaFuncSetAttribute(proj_ldm_kernel,
                         cudaFuncAttributeMaxDynamicSharedMemorySize, PROJ_SMEM);

    float *Qrp, *Qp, *Kp, *Vp, *Op, *Wtp;
    cudaGetSymbolAddress((void**)&Qrp, g_Qr);
    cudaGetSymbolAddress((void**)&Qp, g_Q);
    cudaGetSymbolAddress((void**)&Kp, g_K);
    cudaGetSymbolAddress((void**)&Vp, g_V);
    cudaGetSymbolAddress((void**)&Op, g_O);
    cudaGetSymbolAddress((void**)&Wtp, g_Wt);
    const float *W0 = Wtp, *W1 = Wtp + (size_t)EMBED * EMBED,
                *W2 = Wtp + 2 * (size_t)EMBED * EMBED, *W3 = Wtp + 3 * (size_t)EMBED * EMBED;

    round_query_kernel<<<(MROWS * EMBED) / (256 * 4), 256>>>(query);

    dim3 gTW(EMBED / 32, EMBED / 32, 4);
    transpose_w_kernel<<<gTW, 256>>>(wq, wk, wv, wo);

    // fused QKV projection: grid (8 n, 32 m, 3 z); round all three outputs
    dim3 gQKV(EMBED / 128, MROWS / 128, 3);
    proj_ldm_kernel<<<gQKV, 256, PROJ_SMEM>>>(Qrp, W0, W1, W2, bq, bk, bv, Qp, Kp, Vp, 0x7);

    norms_kernel<<<(B_BATCH * HEADS * SEQ) / 8, 256>>>();

    dim3 gTV(EMBED / 32, SEQ / 32, B_BATCH);
    transpose_v_kernel<<<gTV, 256>>>();

    dim3 gAtt(SEQ / 128, B_BATCH * HEADS);    // (16, 32)
    attention_kernel<<<gAtt, 256, SM_ATT_BYTES>>>(temperature);

    // output projection: no rounding
    dim3 gOut(EMBED / 128, MROWS / 128, 1);
    proj_ldm_kernel<<<gOut, 256, PROJ_SMEM>>>(Op, W3, W3, W3, bo, bo, bo, out, out, out, 0x0);
}

// round 11
// speedup vs baseline: 1.2580x; 1.0007x over previous
#include <cuda_runtime.h>
#include <cstdint>

#define B_BATCH 2
#define SEQ 2048
#define EMBED 1024
#define HEADS 16
#define HDIM 64
#define MROWS (B_BATCH * SEQ)   // 4096

// ---------------- scratch (device globals: allocation-free) ----------------
__device__ float g_Qr[(size_t)MROWS * EMBED];                  // tf32-rounded query
__device__ float g_Q[(size_t)MROWS * EMBED];
__device__ float g_K[(size_t)MROWS * EMBED];
__device__ float g_V[(size_t)MROWS * EMBED];
__device__ float g_O[(size_t)MROWS * EMBED];
__device__ float g_Wt[(size_t)4 * EMBED * EMBED];              // transposed weights (tf32)
__device__ float g_Vt[(size_t)B_BATCH * HEADS * HDIM * SEQ];   // V transposed per head (tf32)
__device__ float g_qsq[(size_t)B_BATCH * HEADS * SEQ];
__device__ float g_ksq[(size_t)B_BATCH * HEADS * SEQ];

// ======================= helpers =======================
__device__ __forceinline__ uint32_t smem_u32(const void* p) {
    uint32_t a;
    asm("{ .reg .u64 t; cvta.to.shared.u64 t, %1; cvt.u32.u64 %0, t; }" : "=r"(a) : "l"(p));
    return a;
}
__device__ __forceinline__ float to_tf32(float x) {
    float r; asm("cvt.rna.tf32.f32 %0, %1;" : "=f"(r) : "f"(x)); return r;
}
__device__ __forceinline__ void cp_async16(uint32_t dst, const void* src) {
    asm volatile("cp.async.cg.shared.global [%0], [%1], 16;" :: "r"(dst), "l"(src));
}
#define CP_COMMIT() asm volatile("cp.async.commit_group;" ::: "memory")
#define CP_WAIT0()  asm volatile("cp.async.wait_group 0;" ::: "memory")
#define CP_WAIT1()  asm volatile("cp.async.wait_group 1;" ::: "memory")

// mma.sync m16n8k8 tf32: D += A*B  (A row-major m16k8, B col-major k8n8)
__device__ __forceinline__ void mma_tf32(float* d, const uint32_t* a, const uint32_t* b) {
    asm volatile(
        "mma.sync.aligned.m16n8k8.row.col.f32.tf32.tf32.f32 "
        "{%0,%1,%2,%3}, {%4,%5,%6,%7}, {%8,%9}, {%0,%1,%2,%3};"
        : "+f"(d[0]), "+f"(d[1]), "+f"(d[2]), "+f"(d[3])
        : "r"(a[0]), "r"(a[1]), "r"(a[2]), "r"(a[3]), "r"(b[0]), "r"(b[1]));
}
__device__ __forceinline__ uint32_t ldsf(const float* p) { return __float_as_uint(*p); }

__device__ __forceinline__ void ldmx4(uint32_t* r, uint32_t addr) {
    asm volatile("ldmatrix.sync.aligned.m8n8.x4.shared.b16 {%0,%1,%2,%3}, [%4];"
        : "=r"(r[0]), "=r"(r[1]), "=r"(r[2]), "=r"(r[3]) : "r"(addr));
}

// ======================= round query to tf32 =======================
__global__ __launch_bounds__(256) void round_query_kernel(const float* __restrict__ in)
{
    size_t i = ((size_t)blockIdx.x * 256 + threadIdx.x) * 4;
    float4 v = *(const float4*)&in[i];
    v.x = to_tf32(v.x); v.y = to_tf32(v.y); v.z = to_tf32(v.z); v.w = to_tf32(v.w);
    *(float4*)&g_Qr[i] = v;
}

// ======================= transpose weights (+tf32 round) =======================
__global__ __launch_bounds__(256) void transpose_w_kernel(
    const float* __restrict__ wq, const float* __restrict__ wk,
    const float* __restrict__ wv, const float* __restrict__ wo)
{
    __shared__ float t[32][33];
    const int z = blockIdx.z;
    const float* W = (z == 0) ? wq : (z == 1) ? wk : (z == 2) ? wv : wo;
    float* Out = g_Wt + (size_t)z * EMBED * EMBED;
    const int k0 = blockIdx.x * 32, n0 = blockIdx.y * 32;
    const int tx = threadIdx.x & 31, ty = threadIdx.x >> 5;
#pragma unroll
    for (int i = 0; i < 4; i++)
        t[ty + i * 8][tx] = W[(size_t)(k0 + ty + i * 8) * EMBED + n0 + tx];
    __syncthreads();
#pragma unroll
    for (int i = 0; i < 4; i++)
        Out[(size_t)(n0 + ty + i * 8) * EMBED + k0 + tx] = to_tf32(t[tx][ty + i * 8]);
}

// ======================= transpose V per head (+tf32 round) =======================
__global__ __launch_bounds__(256) void transpose_v_kernel()
{
    __shared__ float t[32][33];
    const int b = blockIdx.z;
    const int e0 = blockIdx.x * 32, s0 = blockIdx.y * 32;
    const int tx = threadIdx.x & 31, ty = threadIdx.x >> 5;
#pragma unroll
    for (int i = 0; i < 4; i++)
        t[ty + i * 8][tx] = g_V[(size_t)(b * SEQ + s0 + ty + i * 8) * EMBED + e0 + tx];
    __syncthreads();
#pragma unroll
    for (int i = 0; i < 4; i++) {
        int e = e0 + ty + i * 8;
        int s = s0 + tx;
        g_Vt[(size_t)(b * HEADS + (e >> 6)) * HDIM * SEQ + (size_t)(e & 63) * SEQ + s] =
            to_tf32(t[tx][ty + i * 8]);
    }
}

// ======================= per-row squared norms =======================
__global__ __launch_bounds__(256) void norms_kernel()
{
    int gw = (blockIdx.x * 256 + threadIdx.x) >> 5;
    int lane = threadIdx.x & 31;
    int z = gw / SEQ, s = gw % SEQ;
    int b = z / HEADS, h = z % HEADS;
    size_t off = (size_t)(b * SEQ + s) * EMBED + h * HDIM + lane * 2;
    float2 q = *(const float2*)&g_Q[off];
    float2 k = *(const float2*)&g_K[off];
    float qs = q.x * q.x + q.y * q.y;
    float ks = k.x * k.x + k.y * k.y;
#pragma unroll
    for (int o = 16; o > 0; o >>= 1) {
        qs += __shfl_xor_sync(0xffffffffu, qs, o);
        ks += __shfl_xor_sync(0xffffffffu, ks, o);
    }
    if (lane == 0) { g_qsq[gw] = qs; g_ksq[gw] = ks; }
}

// ======================= tf32 mma.sync projection GEMM (128x128, ldmatrix, 3-stage) ======
// Block 128x128, BK=32, 256 threads, 8 warps (64x32 each), 3-stage cp.async.
// Smem: 3 stages x (A 128x36 + B 128x36) floats = 110592 B.
#define PROJ_STAGE_F (128 * 36 * 2)           // floats per stage (A then B)
#define PROJ_SMEM    (3 * PROJ_STAGE_F * 4)   // 110592 bytes

__global__ __launch_bounds__(256, 2) void proj_ldm_kernel(
    const float* __restrict__ A,
    const float* __restrict__ B0, const float* __restrict__ B1, const float* __restrict__ B2,
    const float* __restrict__ bias0, const float* __restrict__ bias1, const float* __restrict__ bias2,
    float* __restrict__ C0, float* __restrict__ C1, float* __restrict__ C2,
    int roundMask)
{
    extern __shared__ __align__(16) float smf[];
    const int z = blockIdx.z;
    const float* Bt = (z == 0) ? B0 : (z == 1) ? B1 : B2;
    const float* bias = (z == 0) ? bias0 : (z == 1) ? bias1 : bias2;
    float* C = (z == 0) ? C0 : (z == 1) ? C1 : C2;
    const bool doRound = (roundMask >> z) & 1;

    const uint32_t sBase = smem_u32(smf);
    const int tid = threadIdx.x, lane = tid & 31, warp = tid >> 5;
    const int g = lane >> 2, tg = lane & 3;
    const int m0 = blockIdx.y * 128, n0 = blockIdx.x * 128;
    const int mw = (warp >> 2) * 64, nw = (warp & 3) * 32;

    // ldmatrix lane offsets (bytes) within a stage
    const uint32_t aOff = ((mw + (lane & 15)) * 36 + ((lane >> 4) << 2)) * 4;
    const uint32_t bOff = 18432 +
        ((nw + (lane & 7) + ((lane >> 4) << 3)) * 36 + (((lane >> 3) & 1) << 2)) * 4;

    float acc[4][4][4];
#pragma unroll
    for (int mi = 0; mi < 4; mi++)
#pragma unroll
        for (int ni = 0; ni < 4; ni++)
#pragma unroll
            for (int c = 0; c < 4; c++) acc[mi][ni][c] = 0.f;

    auto issue = [&](int kc) {
        const uint32_t sb = sBase + (kc % 3) * (PROJ_STAGE_F * 4);
        const int k0 = kc * 32;
#pragma unroll
        for (int it = 0; it < 4; it++) {
            int idx = tid + it * 256;
            int r = idx >> 3, c = idx & 7;
            cp_async16(sb + r * 144 + c * 16, &A[(size_t)(m0 + r) * EMBED + k0 + c * 4]);
            cp_async16(sb + 18432 + r * 144 + c * 16, &Bt[(size_t)(n0 + r) * EMBED + k0 + c * 4]);
        }
        CP_COMMIT();
    };

    issue(0); issue(1);
    for (int kc = 0; kc < 32; kc++) {
        if (kc == 31) { CP_WAIT0(); } else { CP_WAIT1(); }
        __syncthreads();
        if (kc + 2 < 32) issue(kc + 2);
        const uint32_t sb = sBase + (kc % 3) * (PROJ_STAGE_F * 4);
#pragma unroll
        for (int ks = 0; ks < 4; ks++) {
            const uint32_t kb = ks * 32;     // 8 floats
            uint32_t af[4][4], bf[4][2];
#pragma unroll
            for (int mi = 0; mi < 4; mi++)
                ldmx4(af[mi], sb + aOff + mi * 2304 + kb);   // 16 rows * 144 B
            {
                uint32_t t0[4], t1[4];
                ldmx4(t0, sb + bOff + kb);
                ldmx4(t1, sb + bOff + 2304 + kb);
                bf[0][0] = t0[0]; bf[0][1] = t0[1]; bf[1][0] = t0[2]; bf[1][1] = t0[3];
                bf[2][0] = t1[0]; bf[2][1] = t1[1]; bf[3][0] = t1[2]; bf[3][1] = t1[3];
            }
#pragma unroll
            for (int mi = 0; mi < 4; mi++)
#pragma unroll
                for (int ni = 0; ni < 4; ni++)
                    mma_tf32(acc[mi][ni], af[mi], bf[ni]);
        }
        __syncthreads();
    }

#pragma unroll
    for (int mi = 0; mi < 4; mi++)
#pragma unroll
        for (int ni = 0; ni < 4; ni++) {
            int row = m0 + mw + mi * 16 + g;
            int col = n0 + nw + ni * 8 + tg * 2;
            float b0 = bias[col], b1 = bias[col + 1];
            float2 v0, v1;
            v0.x = acc[mi][ni][0] + b0; v0.y = acc[mi][ni][1] + b1;
            v1.x = acc[mi][ni][2] + b0; v1.y = acc[mi][ni][3] + b1;
            if (doRound) {
                v0.x = to_tf32(v0.x); v0.y = to_tf32(v0.y);
                v1.x = to_tf32(v1.x); v1.y = to_tf32(v1.y);
            }
            *(float2*)&C[(size_t)row * EMBED + col] = v0;
            *(float2*)&C[(size_t)(row + 8) * EMBED + col] = v1;
        }
}

// ======================= fused attention (tf32 mma.sync, ldmatrix loads) =======================
// Per block: one (b,h), one 128-row q-tile; 16 k-tiles of 128. R6 structure.
// Smem (floats): Qs[128][68] | Ks[128][68] | Vts[64][132] | Ps[128][132] | ksq[128] | lsum[128][2]
#define SM_Q    0
#define SM_K    34816
#define SM_VT   69632
#define SM_P    103424
#define SM_KSQ  171008
#define SM_LSUM 171520
#define SM_ATT_BYTES 172544

__global__ __launch_bounds__(256, 1) void attention_kernel(const float* __restrict__ tempPtr)
{
    extern __shared__ __align__(16) char smc[];
    float* Ps  = (float*)(smc + SM_P);
    float* ksq = (float*)(smc + SM_KSQ);
    float* lsum = (float*)(smc + SM_LSUM);
    const uint32_t sQ = smem_u32(smc + SM_Q);
    const uint32_t sK = smem_u32(smc + SM_K);
    const uint32_t sVT = smem_u32(smc + SM_VT);
    const uint32_t sP = smem_u32(smc + SM_P);

    const int tid = threadIdx.x, lane = tid & 31, warp = tid >> 5;
    const int g = lane >> 2, tg = lane & 3;
    const int mw = (warp >> 1) * 32;
    const int nhalf = warp & 1;
    const int nw = nhalf * 64;
    const int nwo = nhalf * 32;

    // ldmatrix lane base addresses (bytes)
    // A-frag style (m16k8): rows (lane&15), k-half (lane>>4)
    const uint32_t aQb = sQ + (mw + (lane & 15)) * 272 + ((lane >> 4) << 4);
    const uint32_t aPb = sP + (mw + (lane & 15)) * 528 + ((lane >> 4) << 4);
    // B-frag style (two n8 tiles per x4): rows (lane&7)+((lane>>4)<<3), k-half (lane>>3)&1
    const uint32_t bKb = sK + (nw + (lane & 7) + ((lane >> 4) << 3)) * 272 + (((lane >> 3) & 1) << 4);
    const uint32_t bVb = sVT + (nwo + (lane & 7) + ((lane >> 4) << 3)) * 528 + (((lane >> 3) & 1) << 4);

    const int z = blockIdx.y;
    const int b = z / HEADS, h = z % HEADS;
    const int q0 = blockIdx.x * 128;
    const float invT = 1.0f / (*tempPtr);

#pragma unroll
    for (int it = 0; it < 8; it++) {
        int idx = tid + it * 256;
        int r = idx >> 4, c = idx & 15;
        cp_async16(sQ + r * 272 + c * 16,
                   &g_Q[(size_t)(b * SEQ + q0 + r) * EMBED + h * HDIM + c * 4]);
    }
    CP_COMMIT();

    float qqv[4];
#pragma unroll
    for (int mi = 0; mi < 2; mi++) {
        qqv[mi * 2 + 0] = g_qsq[(size_t)z * SEQ + q0 + mw + mi * 16 + g];
        qqv[mi * 2 + 1] = g_qsq[(size_t)z * SEQ + q0 + mw + mi * 16 + g + 8];
    }

    float oacc[2][4][4];
#pragma unroll
    for (int mi = 0; mi < 2; mi++)
#pragma unroll
        for (int ni = 0; ni < 4; ni++)
#pragma unroll
            for (int c = 0; c < 4; c++) oacc[mi][ni][c] = 0.f;
    float rsum[4] = {0.f, 0.f, 0.f, 0.f};

    for (int kt = 0; kt < 16; kt++) {
        const int kk0 = kt * 128;
        __syncthreads();
#pragma unroll
        for (int it = 0; it < 8; it++) {
            int idx = tid + it * 256;
            {
                int r = idx >> 4, c = idx & 15;
                cp_async16(sK + r * 272 + c * 16,
                           &g_K[(size_t)(b * SEQ + kk0 + r) * EMBED + h * HDIM + c * 4]);
            }
            {
                int r = idx >> 5, c = idx & 31;
                cp_async16(sVT + r * 528 + c * 16,
                           &g_Vt[(size_t)z * HDIM * SEQ + (size_t)r * SEQ + kk0 + c * 4]);
            }
        }
        CP_COMMIT();
        if (tid < 32) {
            float4 v = ((const float4*)&g_ksq[(size_t)z * SEQ + kk0])[tid];
            ((float4*)ksq)[tid] = v;
        }
        CP_WAIT0();
        __syncthreads();

        // ---- S = Q @ K^T (warp: 32x64), ldmatrix fragment loads ----
        float sacc[2][8][4];
#pragma unroll
        for (int mi = 0; mi < 2; mi++)
#pragma unroll
            for (int nj = 0; nj < 8; nj++)
#pragma unroll
                for (int c = 0; c < 4; c++) sacc[mi][nj][c] = 0.f;
#pragma unroll
        for (int ks = 0; ks < 8; ks++) {
            const uint32_t kb = ks * 32;   // 8 floats
            uint32_t af[2][4], bf[8][2];
            ldmx4(af[0], aQb + kb);
            ldmx4(af[1], aQb + 16 * 272 + kb);
#pragma unroll
            for (int j = 0; j < 4; j++) {
                uint32_t t[4];
                ldmx4(t, bKb + j * 16 * 272 + kb);
                bf[j * 2][0] = t[0]; bf[j * 2][1] = t[1];
                bf[j * 2 + 1][0] = t[2]; bf[j * 2 + 1][1] = t[3];
            }
#pragma unroll
            for (int mi = 0; mi < 2; mi++)
#pragma unroll
                for (int nj = 0; nj < 8; nj++)
                    mma_tf32(sacc[mi][nj], af[mi], bf[nj]);
        }

        // ---- epilogue: p = exp(-max(qq+kk-2s,0)/T), write P ----
#pragma unroll
        for (int mi = 0; mi < 2; mi++) {
            const int rlo = mw + mi * 16 + g, rhi = rlo + 8;
            const float qlo = qqv[mi * 2], qhi = qqv[mi * 2 + 1];
#pragma unroll
            for (int nj = 0; nj < 8; nj++) {
                const int col = nw + nj * 8 + tg * 2;
                const float kc0 = ksq[col], kc1 = ksq[col + 1];
                float p00 = __expf(-fmaxf(qlo + kc0 - 2.f * sacc[mi][nj][0], 0.f) * invT);
                float p01 = __expf(-fmaxf(qlo + kc1 - 2.f * sacc[mi][nj][1], 0.f) * invT);
                float p10 = __expf(-fmaxf(qhi + kc0 - 2.f * sacc[mi][nj][2], 0.f) * invT);
                float p11 = __expf(-fmaxf(qhi + kc1 - 2.f * sacc[mi][nj][3], 0.f) * invT);
                rsum[mi * 2 + 0] += p00 + p01;
                rsum[mi * 2 + 1] += p10 + p11;
                float2 w0 = { to_tf32(p00), to_tf32(p01) };
                float2 w1 = { to_tf32(p10), to_tf32(p11) };
                *(float2*)&Ps[rlo * 132 + col] = w0;
                *(float2*)&Ps[rhi * 132 + col] = w1;
            }
        }
        __syncthreads();

        // ---- O += P @ V (warp: 32x32, k=128), ldmatrix fragment loads ----
#pragma unroll
        for (int ks = 0; ks < 16; ks++) {
            const uint32_t kb = ks * 32;
            uint32_t paf[2][4], vbf[4][2];
            ldmx4(paf[0], aPb + kb);
            ldmx4(paf[1], aPb + 16 * 528 + kb);
#pragma unroll
            for (int j = 0; j < 2; j++) {
                uint32_t t[4];
                ldmx4(t, bVb + j * 16 * 528 + kb);
                vbf[j * 2][0] = t[0]; vbf[j * 2][1] = t[1];
                vbf[j * 2 + 1][0] = t[2]; vbf[j * 2 + 1][1] = t[3];
            }
#pragma unroll
            for (int mi = 0; mi < 2; mi++)
#pragma unroll
                for (int ni = 0; ni < 4; ni++)
                    mma_tf32(oacc[mi][ni], paf[mi], vbf[ni]);
        }
    }

#pragma unroll
    for (int i = 0; i < 4; i++) {
        rsum[i] += __shfl_xor_sync(0xffffffffu, rsum[i], 1);
        rsum[i] += __shfl_xor_sync(0xffffffffu, rsum[i], 2);
    }
    __syncthreads();
    if (tg == 0) {
#pragma unroll
        for (int mi = 0; mi < 2; mi++) {
            lsum[(mw + mi * 16 + g) * 2 + nhalf]     = rsum[mi * 2 + 0];
            lsum[(mw + mi * 16 + g + 8) * 2 + nhalf] = rsum[mi * 2 + 1];
        }
    }
    __syncthreads();

    float linv[4];
#pragma unroll
    for (int mi = 0; mi < 2; mi++) {
        int rlo = mw + mi * 16 + g, rhi = rlo + 8;
        linv[mi * 2 + 0] = 1.f / (lsum[rlo * 2] + lsum[rlo * 2 + 1]);
        linv[mi * 2 + 1] = 1.f / (lsum[rhi * 2] + lsum[rhi * 2 + 1]);
    }

#pragma unroll
    for (int mi = 0; mi < 2; mi++)
#pragma unroll
        for (int ni = 0; ni < 4; ni++) {
            int rlo = mw + mi * 16 + g, rhi = rlo + 8;
            int col = nwo + ni * 8 + tg * 2;
            float2 w0, w1;
            w0.x = to_tf32(oacc[mi][ni][0] * linv[mi * 2]);
            w0.y = to_tf32(oacc[mi][ni][1] * linv[mi * 2]);
            w1.x = to_tf32(oacc[mi][ni][2] * linv[mi * 2 + 1]);
            w1.y = to_tf32(oacc[mi][ni][3] * linv[mi * 2 + 1]);
            *(float2*)&g_O[(size_t)(b * SEQ + q0 + rlo) * EMBED + h * HDIM + col] = w0;
            *(float2*)&g_O[(size_t)(b * SEQ + q0 + rhi) * EMBED + h * HDIM + col] = w1;
        }
}

// ======================= launcher =======================
extern "C" void kernel_launch(void* const* d_in, const int* in_sizes, int n_in,
                              void* d_out, int out_size)
{
    const float* query = (const float*)d_in[0];
    const float* wq = (const float*)d_in[1];
    const float* bq = (const float*)d_in[2];
    const float* wk = (const float*)d_in[3];
    const float* bk = (const float*)d_in[4];
    const float* wv = (const float*)d_in[5];
    const float* bv = (const float*)d_in[6];
    const float* wo = (const float*)d_in[7];
    const float* bo = (const float*)d_in[8];
    const float* temperature = (const float*)d_in[9];
    float* out = (float*)d_out;

    cudaFuncSetAttribute(attention_kernel,
                         cudaFuncAttributeMaxDynamicSharedMemorySize, SM_ATT_BYTES);
    cudaFuncSetAttribute(proj_ldm_kernel,
                         cudaFuncAttributeMaxDynamicSharedMemorySize, PROJ_SMEM);

    float *Qrp, *Qp, *Kp, *Vp, *Op, *Wtp;
    cudaGetSymbolAddress((void**)&Qrp, g_Qr);
    cudaGetSymbolAddress((void**)&Qp, g_Q);
    cudaGetSymbolAddress((void**)&Kp, g_K);
    cudaGetSymbolAddress((void**)&Vp, g_V);
    cudaGetSymbolAddress((void**)&Op, g_O);
    cudaGetSymbolAddress((void**)&Wtp, g_Wt);
    const float *W0 = Wtp, *W1 = Wtp + (size_t)EMBED * EMBED,
                *W2 = Wtp + 2 * (size_t)EMBED * EMBED, *W3 = Wtp + 3 * (size_t)EMBED * EMBED;

    round_query_kernel<<<(MROWS * EMBED) / (256 * 4), 256>>>(query);

    dim3 gTW(EMBED / 32, EMBED / 32, 4);
    transpose_w_kernel<<<gTW, 256>>>(wq, wk, wv, wo);

    // fused QKV projection: grid (8 n, 32 m, 3 z); round all three outputs
    dim3 gQKV(EMBED / 128, MROWS / 128, 3);
    proj_ldm_kernel<<<gQKV, 256, PROJ_SMEM>>>(Qrp, W0, W1, W2, bq, bk, bv, Qp, Kp, Vp, 0x7);

    norms_kernel<<<(B_BATCH * HEADS * SEQ) / 8, 256>>>();

    dim3 gTV(EMBED / 32, SEQ / 32, B_BATCH);
    transpose_v_kernel<<<gTV, 256>>>();

    dim3 gAtt(SEQ / 128, B_BATCH * HEADS);    // (16, 32)
    attention_kernel<<<gAtt, 256, SM_ATT_BYTES>>>(temperature);

    // output projection: no rounding
    dim3 gOut(EMBED / 128, MROWS / 128, 1);
    proj_ldm_kernel<<<gOut, 256, PROJ_SMEM>>>(Op, W3, W3, W3, bo, bo, bo, out, out, out, 0x0);
}